// round 5
// baseline (speedup 1.0000x reference)
#include <cuda_runtime.h>

// FINN_Burger2D: out = flux(u, a(u)) where a(u) = MLP(1->32->32->1, tanh, no bias)
// Inputs (metadata order): u[2048*2048] f32, W1[32], W2[32*32], W3[32], D[1], BC[2], stencil[2]
// Output: f32 [2048*2048]
//
// Strategy: a(u) depends only on the scalar u -> tabulate a over u in [-8,8]
// (32768 intervals, exact tanhf MLP at nodes), then the main kernel does a
// linear-interp lookup from a shared-memory copy of the table + the 4-neighbor
// flux. Turns a compute-bound MLP kernel into a ~32MB memory-bound stencil.

#define NXD 2048
#define NYD 2048
#define TSIZE 32768
#define T_LO (-8.0f)
#define T_HI (8.0f)

__device__ float g_table[TSIZE + 1];

// ---------------------------------------------------------------------------
// Prologue: exact MLP evaluation at 32769 grid nodes.
// ---------------------------------------------------------------------------
__global__ void build_table_kernel(const float* __restrict__ W1,
                                   const float* __restrict__ W2,
                                   const float* __restrict__ W3) {
    int idx = blockIdx.x * blockDim.x + threadIdx.x;
    if (idx > TSIZE) return;
    float x = T_LO + (T_HI - T_LO) * ((float)idx * (1.0f / (float)TSIZE));

    float h1[32];
#pragma unroll
    for (int j = 0; j < 32; j++) h1[j] = tanhf(x * W1[j]);

    float a = 0.0f;
#pragma unroll 4
    for (int j = 0; j < 32; j++) {
        float acc = 0.0f;
#pragma unroll
        for (int k = 0; k < 32; k++) acc = fmaf(h1[k], W2[k * 32 + j], acc);
        a = fmaf(tanhf(acc), W3[j], a);
    }
    g_table[idx] = a;
}

// ---------------------------------------------------------------------------
// Main: persistent grid, float4-vectorized flux with smem table lookup.
// ---------------------------------------------------------------------------
__global__ __launch_bounds__(1024, 1)
void flux_kernel(const float* __restrict__ u,
                 const float* __restrict__ D,
                 const float* __restrict__ BC,
                 const float* __restrict__ st,
                 float* __restrict__ out) {
    extern __shared__ float s_tab[];  // TSIZE+1 floats = 131076 bytes
    for (int k = threadIdx.x; k <= TSIZE; k += blockDim.x)
        s_tab[k] = g_table[k];
    __syncthreads();

    const float d   = D[0];
    const float bc0 = BC[0];
    const float bc1 = BC[1];
    const float s0  = st[0];
    const float s1  = st[1];
    const float inv = 100.0f;                       // 1/DX == 1/DY
    const float scale = (float)TSIZE / (T_HI - T_LO);  // 2048

    const int nchunks = NXD * NYD / 4;   // 1,048,576 float4 chunks
    const int stride  = gridDim.x * blockDim.x;

    for (int c = blockIdx.x * blockDim.x + threadIdx.x; c < nchunks; c += stride) {
        const int i    = c >> 9;          // NYD/4 = 512 chunks per row
        const int jq   = c & 511;
        const int base = c * 4;           // = i*NYD + jq*4

        float4 uc = *(const float4*)(u + base);
        float4 upv, unv;
        if (i > 0)        upv = *(const float4*)(u + base - NYD);
        else              upv = make_float4(bc0, bc0, bc0, bc0);
        if (i < NXD - 1)  unv = *(const float4*)(u + base + NYD);
        else              unv = make_float4(bc1, bc1, bc1, bc1);
        float um1 = (jq > 0)   ? u[base - 1] : bc0;   // u[i][j0-1]
        float up4 = (jq < 511) ? u[base + 4] : bc1;   // u[i][j0+4]

        float uin[4] = {uc.x, uc.y, uc.z, uc.w};
        float uL[4]  = {upv.x, upv.y, upv.z, upv.w};   // u_left  = row i-1 (bc0)
        float uR[4]  = {unv.x, unv.y, unv.z, unv.w};   // u_right = row i+1 (bc1)
        float uB[4]  = {um1, uc.x, uc.y, uc.z};        // u_bot   = col j-1 (bc0)
        float uT[4]  = {uc.y, uc.z, uc.w, up4};        // u_top   = col j+1 (bc1)

        float4 o;
        float* op = &o.x;
#pragma unroll
        for (int k = 0; k < 4; k++) {
            const float uv = uin[k];

            // a(u) via linear interp from shared table
            float t = (uv - T_LO) * scale;
            t = fmaxf(t, 0.0f);
            int i0 = (int)t;
            if (i0 > TSIZE - 1) i0 = TSIZE - 1;
            float fr = t - (float)i0;
            float a0 = s_tab[i0];
            float a1 = s_tab[i0 + 1];
            float a  = fmaf(fr, a1 - a0, a0);

            const float ap = fmaxf(a, 0.0f);   // relu(a)
            const float am = fminf(a, 0.0f);   // -relu(-a)

            const float su = s0 * uv;
            const float gL = fmaf(s1, uL[k], su);
            const float gR = fmaf(s1, uR[k], su);
            const float gB = fmaf(s1, uB[k], su);
            const float gT = fmaf(s1, uT[k], su);

            // left:  d*gL + ap/DX*gL ; right: d*gR - am/DX*gR
            // bot:   d*gB + ap/DY*gB ; top:   d*gT - am/DY*gT
            op[k] = d * (gL + gR + gB + gT)
                  + inv * (ap * gL - am * gR)
                  + inv * (ap * gB - am * gT);
        }
        *(float4*)(out + base) = o;
    }
}

// ---------------------------------------------------------------------------
extern "C" void kernel_launch(void* const* d_in, const int* in_sizes, int n_in,
                              void* d_out, int out_size) {
    const float* u  = (const float*)d_in[0];
    const float* W1 = (const float*)d_in[1];
    const float* W2 = (const float*)d_in[2];
    const float* W3 = (const float*)d_in[3];
    const float* D  = (const float*)d_in[4];
    const float* BC = (const float*)d_in[5];
    const float* st = (const float*)d_in[6];
    float* out = (float*)d_out;

    (void)in_sizes; (void)n_in; (void)out_size;

    const int smem_bytes = (TSIZE + 1) * (int)sizeof(float);  // 131076
    cudaFuncSetAttribute(flux_kernel,
                         cudaFuncAttributeMaxDynamicSharedMemorySize, smem_bytes);

    build_table_kernel<<<(TSIZE + 1 + 255) / 256, 256>>>(W1, W2, W3);
    flux_kernel<<<148, 1024, smem_bytes>>>(u, D, BC, st, out);
}

// round 6
// speedup vs baseline: 1.7879x; 1.7879x over previous
#include <cuda_runtime.h>

// FINN_Burger2D: out = flux(u, a(u)) where a(u) = MLP(1->32->32->1, tanh, no bias)
// Inputs (metadata order): u[2048*2048] f32, W1[32], W2[32*32], W3[32], D[1], BC[2], stencil[2]
// Output: f32 [2048*2048]
//
// a(u) is a scalar function of a scalar -> tabulate over [-8,8] (4096 intervals,
// exact tanhf MLP at nodes, one WARP per node via shuffle), then flux kernel does
// a single LDS.64 {a, da} linear-interp lookup per point + 4-neighbor upwind flux.

#define NXD 2048
#define NYD 2048
#define TSIZE 4096
#define T_LO (-8.0f)
#define T_HI (8.0f)

__device__ float g_a[TSIZE + 1];

// ---------------------------------------------------------------------------
// Prologue: one warp per table node. lane k computes h1[k]=tanh(x*W1[k]);
// lane j accumulates column j of W2 via shuffles; butterfly-reduce h2*W3.
// ---------------------------------------------------------------------------
__global__ void build_table_kernel(const float* __restrict__ W1,
                                   const float* __restrict__ W2,
                                   const float* __restrict__ W3) {
    const int gtid = blockIdx.x * blockDim.x + threadIdx.x;
    const int node = gtid >> 5;
    const int lane = gtid & 31;
    if (node > TSIZE) return;

    const float x = T_LO + (T_HI - T_LO) * ((float)node * (1.0f / (float)TSIZE));

    const float h1 = tanhf(x * W1[lane]);

    float acc = 0.0f;
#pragma unroll
    for (int k = 0; k < 32; k++)
        acc = fmaf(__shfl_sync(0xffffffffu, h1, k), W2[k * 32 + lane], acc);

    float p = tanhf(acc) * W3[lane];
#pragma unroll
    for (int o = 16; o > 0; o >>= 1)
        p += __shfl_xor_sync(0xffffffffu, p, o);

    if (lane == 0) g_a[node] = p;
}

// ---------------------------------------------------------------------------
// Main: persistent grid, float4-vectorized flux; single float2 smem lookup/pt.
// ---------------------------------------------------------------------------
__global__ __launch_bounds__(512, 3)
void flux_kernel(const float* __restrict__ u,
                 const float* __restrict__ D,
                 const float* __restrict__ BC,
                 const float* __restrict__ st,
                 float* __restrict__ out) {
    extern __shared__ float2 s_tab[];   // TSIZE entries {a_i, a_{i+1}-a_i} = 32KB
    for (int k = threadIdx.x; k < TSIZE; k += blockDim.x) {
        float a0 = g_a[k];
        float a1 = g_a[k + 1];
        s_tab[k] = make_float2(a0, a1 - a0);
    }
    __syncthreads();

    const float d   = D[0];
    const float bc0 = BC[0];
    const float bc1 = BC[1];
    const float s0  = st[0];
    const float s1  = st[1];
    const float inv = 100.0f;                          // 1/DX == 1/DY
    const float scale = (float)TSIZE / (T_HI - T_LO);  // 256

    const int nchunks = NXD * NYD / 4;   // 1,048,576 float4 chunks
    const int stride  = gridDim.x * blockDim.x;

    for (int c = blockIdx.x * blockDim.x + threadIdx.x; c < nchunks; c += stride) {
        const int i    = c >> 9;          // NYD/4 = 512 chunks per row
        const int jq   = c & 511;
        const int base = c * 4;

        float4 uc = *(const float4*)(u + base);
        float4 upv, unv;
        if (i > 0)        upv = *(const float4*)(u + base - NYD);
        else              upv = make_float4(bc0, bc0, bc0, bc0);
        if (i < NXD - 1)  unv = *(const float4*)(u + base + NYD);
        else              unv = make_float4(bc1, bc1, bc1, bc1);
        const float um1 = (jq > 0)   ? u[base - 1] : bc0;   // col j-1 edge
        const float up4 = (jq < 511) ? u[base + 4] : bc1;   // col j+4 edge

        const float uin[4] = {uc.x, uc.y, uc.z, uc.w};
        const float uL[4]  = {upv.x, upv.y, upv.z, upv.w};  // row i-1 (bc0)
        const float uR[4]  = {unv.x, unv.y, unv.z, unv.w};  // row i+1 (bc1)
        const float uB[4]  = {um1, uc.x, uc.y, uc.z};       // col j-1 (bc0)
        const float uT[4]  = {uc.y, uc.z, uc.w, up4};       // col j+1 (bc1)

        float4 o;
        float* op = &o.x;
#pragma unroll
        for (int k = 0; k < 4; k++) {
            const float uv = uin[k];

            // a(u) via single float2 {a, da} interp from shared table
            float t = (uv - T_LO) * scale;
            t = fmaxf(t, 0.0f);
            int i0 = (int)t;
            if (i0 > TSIZE - 1) i0 = TSIZE - 1;
            const float fr = t - (float)i0;
            const float2 e = s_tab[i0];
            const float a  = fmaf(fr, e.y, e.x);

            // coefficients: left/bottom get d + relu(a)/DX; right/top get d - (-relu(-a))/DX
            const float cp = fmaf(fmaxf(a, 0.0f),  inv, d);
            const float cm = fmaf(fminf(a, 0.0f), -inv, d);

            // gL+gB = 2*s0*u + s1*(uL+uB);  gR+gT = 2*s0*u + s1*(uR+uT)
            const float su2 = 2.0f * s0 * uv;
            const float gLB = fmaf(s1, uL[k] + uB[k], su2);
            const float gRT = fmaf(s1, uR[k] + uT[k], su2);

            op[k] = cp * gLB + cm * gRT;
        }
        *(float4*)(out + base) = o;
    }
}

// ---------------------------------------------------------------------------
extern "C" void kernel_launch(void* const* d_in, const int* in_sizes, int n_in,
                              void* d_out, int out_size) {
    const float* u  = (const float*)d_in[0];
    const float* W1 = (const float*)d_in[1];
    const float* W2 = (const float*)d_in[2];
    const float* W3 = (const float*)d_in[3];
    const float* D  = (const float*)d_in[4];
    const float* BC = (const float*)d_in[5];
    const float* st = (const float*)d_in[6];
    float* out = (float*)d_out;

    (void)in_sizes; (void)n_in; (void)out_size;

    const int smem_bytes = TSIZE * (int)sizeof(float2);  // 32768

    // (TSIZE+1) warps, 8 warps per block
    const int build_warps  = TSIZE + 1;
    const int build_blocks = (build_warps + 7) / 8;
    build_table_kernel<<<build_blocks, 256>>>(W1, W2, W3);

    flux_kernel<<<148 * 3, 512, smem_bytes>>>(u, D, BC, st, out);
}

// round 7
// speedup vs baseline: 1.9849x; 1.1102x over previous
#include <cuda_runtime.h>

// FINN_Burger2D: out = flux(u, a(u)) where a(u) = MLP(1->32->32->1, tanh, no bias)
// Inputs: u[2048*2048] f32, W1[32], W2[32*32], W3[32], D[1], BC[2], stencil[2]
// Output: f32 [2048*2048]
//
// a(u) is scalar->scalar: tabulate over [-8,8] (1024 intervals, exact tanhf MLP
// at nodes; one warp per node with smem h1 broadcast), then flux kernel does one
// LDS.64 {a, da} interp per point + 4-neighbor upwind flux. Column-neighbor
// scalars come from warp shuffles (lanes own consecutive chunks of one row).

#define NXD 2048
#define NYD 2048
#define TSIZE 1024
#define T_LO (-8.0f)
#define T_HI (8.0f)

__device__ float g_a[TSIZE + 1];

// ---------------------------------------------------------------------------
// Prologue: one warp per node. lane k computes h1[k], broadcast via smem
// (conflict-free LDS broadcasts -> 32 independent FMAs, no serial shfl chain).
// ---------------------------------------------------------------------------
__global__ __launch_bounds__(256)
void build_table_kernel(const float* __restrict__ W1,
                        const float* __restrict__ W2,
                        const float* __restrict__ W3) {
    __shared__ float h1s[8][32];
    const int w    = threadIdx.x >> 5;
    const int lane = threadIdx.x & 31;
    const int node = blockIdx.x * 8 + w;
    if (node > TSIZE) return;

    const float x = T_LO + (T_HI - T_LO) * ((float)node * (1.0f / (float)TSIZE));

    h1s[w][lane] = tanhf(x * W1[lane]);
    __syncwarp();

    float acc = 0.0f;
#pragma unroll
    for (int k = 0; k < 32; k++)
        acc = fmaf(h1s[w][k], W2[k * 32 + lane], acc);

    float p = tanhf(acc) * W3[lane];
#pragma unroll
    for (int o = 16; o > 0; o >>= 1)
        p += __shfl_xor_sync(0xffffffffu, p, o);

    if (lane == 0) g_a[node] = p;
}

// ---------------------------------------------------------------------------
// Main: persistent grid, float4 chunks; warp-shuffle column neighbors;
// single float2 smem lookup per point.
// ---------------------------------------------------------------------------
__global__ __launch_bounds__(512, 3)
void flux_kernel(const float* __restrict__ u,
                 const float* __restrict__ D,
                 const float* __restrict__ BC,
                 const float* __restrict__ st,
                 float* __restrict__ out) {
    extern __shared__ float2 s_tab[];   // TSIZE entries {a_i, da_i} = 8KB
    for (int k = threadIdx.x; k < TSIZE; k += blockDim.x) {
        float a0 = g_a[k];
        float a1 = g_a[k + 1];
        s_tab[k] = make_float2(a0, a1 - a0);
    }
    __syncthreads();

    const float d   = D[0];
    const float bc0 = BC[0];
    const float bc1 = BC[1];
    const float s0  = st[0];
    const float s1  = st[1];
    const float inv = 100.0f;                          // 1/DX == 1/DY
    const float scale = (float)TSIZE / (T_HI - T_LO);  // 64

    const int lane    = threadIdx.x & 31;
    const int nchunks = NXD * NYD / 4;   // 1,048,576 float4 chunks
    const int stride  = gridDim.x * blockDim.x;

    // Lanes of a warp hold 32 consecutive chunks of one row (512 chunks/row,
    // warp bases are multiples of 32 -> warps never straddle a row; the
    // c < nchunks boundary is also warp-uniform since nchunks % 32 == 0).
    for (int c = blockIdx.x * blockDim.x + threadIdx.x; c < nchunks; c += stride) {
        const int i    = c >> 9;          // row (512 chunks per row)
        const int jq   = c & 511;
        const int base = c * 4;

        float4 uc = *(const float4*)(u + base);
        float4 upv, unv;
        if (i > 0)        upv = *(const float4*)(u + base - NYD);
        else              upv = make_float4(bc0, bc0, bc0, bc0);
        if (i < NXD - 1)  unv = *(const float4*)(u + base + NYD);
        else              unv = make_float4(bc1, bc1, bc1, bc1);

        // column-edge scalars from neighbor lanes; real loads only at warp ends
        float um1 = __shfl_up_sync(0xffffffffu, uc.w, 1);    // u[base-1]
        float up4 = __shfl_down_sync(0xffffffffu, uc.x, 1);  // u[base+4]
        if (lane == 0)  um1 = (jq > 0)   ? u[base - 1] : bc0;
        if (lane == 31) up4 = (jq < 511) ? u[base + 4] : bc1;

        const float uin[4] = {uc.x, uc.y, uc.z, uc.w};
        const float uL[4]  = {upv.x, upv.y, upv.z, upv.w};  // row i-1 (bc0)
        const float uR[4]  = {unv.x, unv.y, unv.z, unv.w};  // row i+1 (bc1)
        const float uB[4]  = {um1, uc.x, uc.y, uc.z};       // col j-1 (bc0)
        const float uT[4]  = {uc.y, uc.z, uc.w, up4};       // col j+1 (bc1)

        float4 o;
        float* op = &o.x;
#pragma unroll
        for (int k = 0; k < 4; k++) {
            const float uv = uin[k];

            // a(u): single float2 {a, da} interp from shared table
            float t = (uv - T_LO) * scale;
            t = fmaxf(t, 0.0f);
            int i0 = (int)t;
            if (i0 > TSIZE - 1) i0 = TSIZE - 1;
            const float fr = t - (float)i0;
            const float2 e = s_tab[i0];
            const float a  = fmaf(fr, e.y, e.x);

            const float cp = fmaf(fmaxf(a, 0.0f),  inv, d);  // d + relu(a)/DX
            const float cm = fmaf(fminf(a, 0.0f), -inv, d);  // d - (-relu(-a))/DX

            const float su2 = 2.0f * s0 * uv;
            const float gLB = fmaf(s1, uL[k] + uB[k], su2);
            const float gRT = fmaf(s1, uR[k] + uT[k], su2);

            op[k] = cp * gLB + cm * gRT;
        }
        *(float4*)(out + base) = o;
    }
}

// ---------------------------------------------------------------------------
extern "C" void kernel_launch(void* const* d_in, const int* in_sizes, int n_in,
                              void* d_out, int out_size) {
    const float* u  = (const float*)d_in[0];
    const float* W1 = (const float*)d_in[1];
    const float* W2 = (const float*)d_in[2];
    const float* W3 = (const float*)d_in[3];
    const float* D  = (const float*)d_in[4];
    const float* BC = (const float*)d_in[5];
    const float* st = (const float*)d_in[6];
    float* out = (float*)d_out;

    (void)in_sizes; (void)n_in; (void)out_size;

    const int smem_bytes = TSIZE * (int)sizeof(float2);  // 8192

    // 1025 nodes, one warp each, 8 warps per block
    build_table_kernel<<<(TSIZE + 1 + 7) / 8, 256>>>(W1, W2, W3);

    flux_kernel<<<148 * 3, 512, smem_bytes>>>(u, D, BC, st, out);
}

// round 10
// speedup vs baseline: 2.3033x; 1.1604x over previous
#include <cuda_runtime.h>

// FINN_Burger2D: out = flux(u, a(u)) where a(u) = MLP(1->32->32->1, tanh, no bias)
// Inputs: u[2048*2048] f32, W1[32], W2[32*32], W3[32], D[1], BC[2], stencil[2]
// Output: f32 [2048*2048]
//
// a(u) is scalar->scalar: tabulate {a, da} over [-8,8] (1024 intervals, exact
// tanhf MLP at both interval endpoints per warp), then flux kernel does one 8B
// __ldg interp per point (table stays hot in L1) + 4-neighbor upwind flux.
// Flux uses register-rolling vertical strips (8 rows/thread): each row of u is
// loaded ~1.25x instead of 3x. Column-neighbor scalars come from warp shuffles.

#define NXD 2048
#define NYD 2048
#define TSIZE 1024
#define T_LO (-8.0f)
#define T_HI (8.0f)
#define HROWS 8

__device__ float2 g_tab[TSIZE];   // {a_i, a_{i+1}-a_i}

// ---------------------------------------------------------------------------
// Prologue: one warp per interval; evaluates MLP at both endpoints with two
// interleaved accumulators (ILP), writes the float2 entry directly.
// ---------------------------------------------------------------------------
__global__ __launch_bounds__(256)
void build_table_kernel(const float* __restrict__ W1,
                        const float* __restrict__ W2,
                        const float* __restrict__ W3) {
    __shared__ float h1s[8][2][32];
    const int w    = threadIdx.x >> 5;
    const int lane = threadIdx.x & 31;
    const int node = blockIdx.x * 8 + w;
    if (node >= TSIZE) return;

    const float step = (T_HI - T_LO) / (float)TSIZE;
    const float x0 = T_LO + step * (float)node;
    const float x1 = x0 + step;

    const float w1 = W1[lane];
    h1s[w][0][lane] = tanhf(x0 * w1);
    h1s[w][1][lane] = tanhf(x1 * w1);
    __syncwarp();

    float acc0 = 0.0f, acc1 = 0.0f;
#pragma unroll
    for (int k = 0; k < 32; k++) {
        const float wv = W2[k * 32 + lane];
        acc0 = fmaf(h1s[w][0][k], wv, acc0);
        acc1 = fmaf(h1s[w][1][k], wv, acc1);
    }
    const float w3 = W3[lane];
    float p0 = tanhf(acc0) * w3;
    float p1 = tanhf(acc1) * w3;
#pragma unroll
    for (int o = 16; o > 0; o >>= 1) {
        p0 += __shfl_xor_sync(0xffffffffu, p0, o);
        p1 += __shfl_xor_sync(0xffffffffu, p1, o);
    }
    if (lane == 0) g_tab[node] = make_float2(p0, p1 - p0);
}

// ---------------------------------------------------------------------------
// Main: 1024 blocks x 128 thr. Block = quarter-row (128 chunks) x 8-row band.
// Each thread register-rolls down 8 rows of its fixed float4 column-chunk.
// ---------------------------------------------------------------------------
__global__ __launch_bounds__(128)
void flux_kernel(const float* __restrict__ u,
                 const float* __restrict__ D,
                 const float* __restrict__ BC,
                 const float* __restrict__ st,
                 float* __restrict__ out) {
    const float d   = D[0];
    const float bc0 = BC[0];
    const float bc1 = BC[1];
    const float s0  = st[0];
    const float s1  = st[1];
    const float inv = 100.0f;                          // 1/DX == 1/DY
    const float scale = (float)TSIZE / (T_HI - T_LO);  // 64

    const int band = blockIdx.x >> 2;          // 0..255 (row band)
    const int q    = blockIdx.x & 3;           // quarter-row
    const int lane = threadIdx.x & 31;
    const int jq   = q * 128 + threadIdx.x;    // chunk column 0..511
    const int col  = jq * 4;
    const int r0   = band * HROWS;

    float4 up, cur;
    if (r0 > 0) up = *(const float4*)(u + (r0 - 1) * NYD + col);
    else        up = make_float4(bc0, bc0, bc0, bc0);
    cur = *(const float4*)(u + r0 * NYD + col);

#pragma unroll
    for (int h = 0; h < HROWS; h++) {
        const int r       = r0 + h;
        const int rowbase = r * NYD + col;

        float4 down;
        if (r < NXD - 1) down = *(const float4*)(u + rowbase + NYD);
        else             down = make_float4(bc1, bc1, bc1, bc1);

        // column-edge scalars from neighbor lanes; real loads only at warp ends
        float um1 = __shfl_up_sync(0xffffffffu, cur.w, 1);    // u[rowbase-1]
        float up4 = __shfl_down_sync(0xffffffffu, cur.x, 1);  // u[rowbase+4]
        if (lane == 0)  um1 = (jq > 0)   ? u[rowbase - 1] : bc0;
        if (lane == 31) up4 = (jq < 511) ? u[rowbase + 4] : bc1;

        const float uin[4] = {cur.x, cur.y, cur.z, cur.w};
        const float uL[4]  = {up.x, up.y, up.z, up.w};      // row i-1 (bc0)
        const float uR[4]  = {down.x, down.y, down.z, down.w}; // row i+1 (bc1)
        const float uB[4]  = {um1, cur.x, cur.y, cur.z};    // col j-1 (bc0)
        const float uT[4]  = {cur.y, cur.z, cur.w, up4};    // col j+1 (bc1)

        float4 o;
        float* op = &o.x;
#pragma unroll
        for (int k = 0; k < 4; k++) {
            const float uv = uin[k];

            // a(u): one 8B {a, da} gather (table hot in L1) + interp
            float t = fmaxf((uv - T_LO) * scale, 0.0f);
            int i0 = (int)t;
            if (i0 > TSIZE - 1) i0 = TSIZE - 1;
            const float fr = t - (float)i0;
            const float2 e = __ldg(&g_tab[i0]);
            const float a  = fmaf(fr, e.y, e.x);

            const float cp = fmaf(fmaxf(a, 0.0f),  inv, d);  // d + relu(a)/DX
            const float cm = fmaf(fminf(a, 0.0f), -inv, d);  // d - (-relu(-a))/DX

            const float su2 = 2.0f * s0 * uv;
            const float gLB = fmaf(s1, uL[k] + uB[k], su2);
            const float gRT = fmaf(s1, uR[k] + uT[k], su2);

            op[k] = cp * gLB + cm * gRT;
        }
        *(float4*)(out + rowbase) = o;

        up = cur; cur = down;   // roll the stencil window
    }
}

// ---------------------------------------------------------------------------
extern "C" void kernel_launch(void* const* d_in, const int* in_sizes, int n_in,
                              void* d_out, int out_size) {
    const float* u  = (const float*)d_in[0];
    const float* W1 = (const float*)d_in[1];
    const float* W2 = (const float*)d_in[2];
    const float* W3 = (const float*)d_in[3];
    const float* D  = (const float*)d_in[4];
    const float* BC = (const float*)d_in[5];
    const float* st = (const float*)d_in[6];
    float* out = (float*)d_out;

    (void)in_sizes; (void)n_in; (void)out_size;

    // 1024 intervals, one warp each, 8 warps per block
    build_table_kernel<<<TSIZE / 8, 256>>>(W1, W2, W3);

    // 256 row-bands x 4 quarter-rows
    flux_kernel<<<(NXD / HROWS) * 4, 128>>>(u, D, BC, st, out);
}